// round 14
// baseline (speedup 1.0000x reference)
#include <cuda_runtime.h>
#include <cuda_fp16.h>

#define N_NODES 50000
#define N_EDGES 800000
#define IN_F 96
#define HID 64
#define N_CLS 32

// Scratch (__device__ globals, allocation-free rule)
__device__ __align__(16) unsigned g_yh[N_NODES * (HID / 2)];     // y half2     (6.4 MB)
__device__ __align__(16) unsigned g_agg1h[N_NODES * (HID / 2)];  // agg1 half2  (6.4 MB)
__device__ __align__(16) unsigned g_zh[N_NODES * (N_CLS / 2)];   // z half2     (3.2 MB)
__device__ __align__(16) unsigned g_agg2h[N_NODES * (N_CLS / 2)];// agg2 half2  (3.2 MB)

__device__ __forceinline__ void red_add_v4h2(unsigned* p, uint4 v) {
    asm volatile("red.global.add.noftz.v4.f16x2 [%0], {%1,%2,%3,%4};"
                 :: "l"(p), "r"(v.x), "r"(v.y), "r"(v.z), "r"(v.w) : "memory");
}

// Zero agg1h only (400k uint4); agg2h is zeroed inside hidden_kernel.
__global__ void zero_kernel() {
    const int n1 = N_NODES * (HID / 2) / 4;    // 400000
    int i = blockIdx.x * blockDim.x + threadIdx.x;
    if (i < n1) ((uint4*)g_agg1h)[i] = make_uint4(0u, 0u, 0u, 0u);
}

// y = x @ W1 [50000 x 64], output packed half2. 50 nodes/block, 160 threads,
// thread computes 5 nodes x 4 cols (= 2 half2).
__global__ void __launch_bounds__(160) gemm_x_kernel(
        const float* __restrict__ x,
        const float* __restrict__ W1) {
    __shared__ float xs[50 * 100];
    __shared__ float ws[IN_F * HID];
    int tid = threadIdx.x;

    for (int i = tid; i < IN_F * HID / 4; i += 160)
        ((float4*)ws)[i] = __ldg((const float4*)W1 + i);

    const float4* xg = (const float4*)x + blockIdx.x * 50 * (IN_F / 4);
    for (int i = tid; i < 50 * (IN_F / 4); i += 160) {
        int r = i / (IN_F / 4);
        int c = i - r * (IN_F / 4);
        *(float4*)&xs[r * 100 + c * 4] = __ldg(xg + i);
    }
    __syncthreads();

    int tx = tid & 15;
    int ty = tid >> 4;
    float acc[5][4];
#pragma unroll
    for (int i = 0; i < 5; ++i)
#pragma unroll
        for (int j = 0; j < 4; ++j) acc[i][j] = 0.f;

    const float* xbase = &xs[ty * 5 * 100];
#pragma unroll 2
    for (int k = 0; k < IN_F; k += 4) {
        float4 wv0 = *(float4*)&ws[(k + 0) * HID + tx * 4];
        float4 wv1 = *(float4*)&ws[(k + 1) * HID + tx * 4];
        float4 wv2 = *(float4*)&ws[(k + 2) * HID + tx * 4];
        float4 wv3 = *(float4*)&ws[(k + 3) * HID + tx * 4];
#pragma unroll
        for (int i = 0; i < 5; ++i) {
            float4 xv = *(float4*)&xbase[i * 100 + k];
            acc[i][0] = fmaf(xv.x, wv0.x, acc[i][0]);
            acc[i][1] = fmaf(xv.x, wv0.y, acc[i][1]);
            acc[i][2] = fmaf(xv.x, wv0.z, acc[i][2]);
            acc[i][3] = fmaf(xv.x, wv0.w, acc[i][3]);
            acc[i][0] = fmaf(xv.y, wv1.x, acc[i][0]);
            acc[i][1] = fmaf(xv.y, wv1.y, acc[i][1]);
            acc[i][2] = fmaf(xv.y, wv1.z, acc[i][2]);
            acc[i][3] = fmaf(xv.y, wv1.w, acc[i][3]);
            acc[i][0] = fmaf(xv.z, wv2.x, acc[i][0]);
            acc[i][1] = fmaf(xv.z, wv2.y, acc[i][1]);
            acc[i][2] = fmaf(xv.z, wv2.z, acc[i][2]);
            acc[i][3] = fmaf(xv.z, wv2.w, acc[i][3]);
            acc[i][0] = fmaf(xv.w, wv3.x, acc[i][0]);
            acc[i][1] = fmaf(xv.w, wv3.y, acc[i][1]);
            acc[i][2] = fmaf(xv.w, wv3.z, acc[i][2]);
            acc[i][3] = fmaf(xv.w, wv3.w, acc[i][3]);
        }
    }
    int n0 = blockIdx.x * 50 + ty * 5;
#pragma unroll
    for (int i = 0; i < 5; ++i) {
        __half2 h0 = __floats2half2_rn(acc[i][0], acc[i][1]);
        __half2 h1 = __floats2half2_rn(acc[i][2], acc[i][3]);
        uint2 u;
        u.x = *(unsigned*)&h0;
        u.y = *(unsigned*)&h1;
        *(uint2*)&g_yh[(n0 + i) * (HID / 2) + tx * 2] = u;
    }
}

// Layer-1 scatter, 4 edges per thread: agg1h[dst] += yh[src].
// 64 halves = 8 x uint4 lanes per edge. All loads front-batched.
__global__ void scatter1_kernel(const int* __restrict__ src,
                                const int* __restrict__ dst) {
    const int E4 = N_EDGES / 4;   // 200000
    int i = blockIdx.x * blockDim.x + threadIdx.x;
    int e = i >> 3;
    int c = i & 7;
    int s0 = __ldg(src + e);
    int d0 = __ldg(dst + e);
    int s1 = __ldg(src + e + E4);
    int d1 = __ldg(dst + e + E4);
    int s2 = __ldg(src + e + 2 * E4);
    int d2 = __ldg(dst + e + 2 * E4);
    int s3 = __ldg(src + e + 3 * E4);
    int d3 = __ldg(dst + e + 3 * E4);
    uint4 v0 = __ldg((const uint4*)g_yh + s0 * 8 + c);
    uint4 v1 = __ldg((const uint4*)g_yh + s1 * 8 + c);
    uint4 v2 = __ldg((const uint4*)g_yh + s2 * 8 + c);
    uint4 v3 = __ldg((const uint4*)g_yh + s3 * 8 + c);
    red_add_v4h2(g_agg1h + d0 * (HID / 2) + c * 4, v0);
    red_add_v4h2(g_agg1h + d1 * (HID / 2) + c * 4, v1);
    red_add_v4h2(g_agg1h + d2 * (HID / 2) + c * 4, v2);
    red_add_v4h2(g_agg1h + d3 * (HID / 2) + c * 4, v3);
}

// Layer-2 scatter, 4 edges per thread: agg2h[dst] += zh[src].
// 32 halves = 4 x uint4 lanes per edge.
__global__ void scatter2_kernel(const int* __restrict__ src,
                                const int* __restrict__ dst) {
    const int E4 = N_EDGES / 4;
    int i = blockIdx.x * blockDim.x + threadIdx.x;
    int e = i >> 2;
    int c = i & 3;
    int s0 = __ldg(src + e);
    int d0 = __ldg(dst + e);
    int s1 = __ldg(src + e + E4);
    int d1 = __ldg(dst + e + E4);
    int s2 = __ldg(src + e + 2 * E4);
    int d2 = __ldg(dst + e + 2 * E4);
    int s3 = __ldg(src + e + 3 * E4);
    int d3 = __ldg(dst + e + 3 * E4);
    uint4 v0 = __ldg((const uint4*)g_zh + s0 * 4 + c);
    uint4 v1 = __ldg((const uint4*)g_zh + s1 * 4 + c);
    uint4 v2 = __ldg((const uint4*)g_zh + s2 * 4 + c);
    uint4 v3 = __ldg((const uint4*)g_zh + s3 * 4 + c);
    red_add_v4h2(g_agg2h + d0 * (N_CLS / 2) + c * 4, v0);
    red_add_v4h2(g_agg2h + d1 * (N_CLS / 2) + c * 4, v1);
    red_add_v4h2(g_agg2h + d2 * (N_CLS / 2) + c * 4, v2);
    red_add_v4h2(g_agg2h + d3 * (N_CLS / 2) + c * 4, v3);
}

// z = relu(agg1 + b1) @ W2  [50000 x 32] -> half2. 32 nodes/block, 128 threads,
// thread computes a 2-node x 4-col register tile. Also zeroes agg2h slice.
__global__ void __launch_bounds__(128) hidden_kernel(
        const float* __restrict__ b1,
        const float* __restrict__ W2) {
    __shared__ float as[32 * 68];      // 8704 B
    __shared__ float ws[HID * N_CLS];  // 8192 B  -> 16.9 KB total
    int tid = threadIdx.x;
    int n0 = blockIdx.x * 32;

    // fold: zero agg2h for this block's 32 nodes (4 uint4 per node = 128).
    {
        int j = n0 * 4 + tid;
        if (j < N_NODES * 4) ((uint4*)g_agg2h)[j] = make_uint4(0u, 0u, 0u, 0u);
    }

    for (int i = tid; i < HID * N_CLS / 4; i += 128)
        ((float4*)ws)[i] = __ldg((const float4*)W2 + i);

    // stage: 32 rows x 8 uint4 chunks; convert fp16->fp32, +b1, relu.
    for (int i = tid; i < 32 * 8; i += 128) {
        int r = i >> 3;
        int c = i & 7;
        int n = n0 + r;
        float4 f0 = make_float4(0.f, 0.f, 0.f, 0.f);
        float4 f1 = f0;
        if (n < N_NODES) {
            uint4 u = __ldg((const uint4*)g_agg1h + n * 8 + c);
            float2 a0 = __half22float2(*(__half2*)&u.x);
            float2 a1 = __half22float2(*(__half2*)&u.y);
            float2 a2 = __half22float2(*(__half2*)&u.z);
            float2 a3 = __half22float2(*(__half2*)&u.w);
            float4 bb0 = __ldg((const float4*)b1 + c * 2);
            float4 bb1 = __ldg((const float4*)b1 + c * 2 + 1);
            f0.x = fmaxf(a0.x + bb0.x, 0.f);
            f0.y = fmaxf(a0.y + bb0.y, 0.f);
            f0.z = fmaxf(a1.x + bb0.z, 0.f);
            f0.w = fmaxf(a1.y + bb0.w, 0.f);
            f1.x = fmaxf(a2.x + bb1.x, 0.f);
            f1.y = fmaxf(a2.y + bb1.y, 0.f);
            f1.z = fmaxf(a3.x + bb1.z, 0.f);
            f1.w = fmaxf(a3.y + bb1.w, 0.f);
        }
        *(float4*)&as[r * 68 + c * 8]     = f0;
        *(float4*)&as[r * 68 + c * 8 + 4] = f1;
    }
    __syncthreads();

    int tx = tid & 7;    // col group (8 x 4 cols = 32)
    int ty = tid >> 3;   // node group (0..15), 2 nodes each
    float acc[2][4];
#pragma unroll
    for (int i = 0; i < 2; ++i)
#pragma unroll
        for (int j = 0; j < 4; ++j) acc[i][j] = 0.f;

    const float* abase = &as[ty * 2 * 68];
#pragma unroll 4
    for (int k = 0; k < HID; k += 4) {
        float4 wv0 = *(float4*)&ws[(k + 0) * N_CLS + tx * 4];
        float4 wv1 = *(float4*)&ws[(k + 1) * N_CLS + tx * 4];
        float4 wv2 = *(float4*)&ws[(k + 2) * N_CLS + tx * 4];
        float4 wv3 = *(float4*)&ws[(k + 3) * N_CLS + tx * 4];
#pragma unroll
        for (int i = 0; i < 2; ++i) {
            float4 xv = *(float4*)&abase[i * 68 + k];
            acc[i][0] = fmaf(xv.x, wv0.x, acc[i][0]);
            acc[i][1] = fmaf(xv.x, wv0.y, acc[i][1]);
            acc[i][2] = fmaf(xv.x, wv0.z, acc[i][2]);
            acc[i][3] = fmaf(xv.x, wv0.w, acc[i][3]);
            acc[i][0] = fmaf(xv.y, wv1.x, acc[i][0]);
            acc[i][1] = fmaf(xv.y, wv1.y, acc[i][1]);
            acc[i][2] = fmaf(xv.y, wv1.z, acc[i][2]);
            acc[i][3] = fmaf(xv.y, wv1.w, acc[i][3]);
            acc[i][0] = fmaf(xv.z, wv2.x, acc[i][0]);
            acc[i][1] = fmaf(xv.z, wv2.y, acc[i][1]);
            acc[i][2] = fmaf(xv.z, wv2.z, acc[i][2]);
            acc[i][3] = fmaf(xv.z, wv2.w, acc[i][3]);
            acc[i][0] = fmaf(xv.w, wv3.x, acc[i][0]);
            acc[i][1] = fmaf(xv.w, wv3.y, acc[i][1]);
            acc[i][2] = fmaf(xv.w, wv3.z, acc[i][2]);
            acc[i][3] = fmaf(xv.w, wv3.w, acc[i][3]);
        }
    }
#pragma unroll
    for (int i = 0; i < 2; ++i) {
        int n = n0 + ty * 2 + i;
        if (n < N_NODES) {
            __half2 h0 = __floats2half2_rn(acc[i][0], acc[i][1]);
            __half2 h1 = __floats2half2_rn(acc[i][2], acc[i][3]);
            uint2 u;
            u.x = *(unsigned*)&h0;
            u.y = *(unsigned*)&h1;
            *(uint2*)&g_zh[n * (N_CLS / 2) + tx * 2] = u;
        }
    }
}

// out = log_softmax(agg2 + b2). Lane handles 2 classes (half2); 16 lanes/node,
// 2 nodes/warp, 16 nodes per 256-thread block.
__global__ void __launch_bounds__(256) lsm_kernel(
        const float* __restrict__ b2,
        float* __restrict__ out) {
    int tid = threadIdx.x;
    int half_lane = tid & 15;             // class pair index
    int n = blockIdx.x * 16 + (tid >> 4); // node
    unsigned u = g_agg2h[n * (N_CLS / 2) + half_lane];
    float2 a = __half22float2(*(__half2*)&u);
    float2 bb = __ldg((const float2*)b2 + half_lane);
    float v0 = a.x + bb.x;
    float v1 = a.y + bb.y;

    float m = fmaxf(v0, v1);
#pragma unroll
    for (int o = 1; o <= 8; o <<= 1) m = fmaxf(m, __shfl_xor_sync(0xffffffffu, m, o));
    float p = __expf(v0 - m) + __expf(v1 - m);
#pragma unroll
    for (int o = 1; o <= 8; o <<= 1) p += __shfl_xor_sync(0xffffffffu, p, o);
    float lp = m + __logf(p);

    float2 r;
    r.x = v0 - lp;
    r.y = v1 - lp;
    ((float2*)out)[n * (N_CLS / 2) + half_lane] = r;
}

extern "C" void kernel_launch(void* const* d_in, const int* in_sizes, int n_in,
                              void* d_out, int out_size) {
    const float* x  = (const float*)d_in[0];
    const int*   ei = (const int*)d_in[1];   // int32 [2, E]
    const float* W1 = (const float*)d_in[2];
    const float* b1 = (const float*)d_in[3];
    const float* W2 = (const float*)d_in[4];
    const float* b2 = (const float*)d_in[5];
    float* out      = (float*)d_out;

    const int* src = ei;
    const int* dst = ei + N_EDGES;

    // 1. zero agg1h (400k uint4)
    zero_kernel<<<(400000 + 255) / 256, 256>>>();

    // 2. y = x @ W1 -> half2
    gemm_x_kernel<<<N_NODES / 50, 160>>>(x, W1);

    // 3. agg1h[dst] += yh[src]  (4 edges/thread, 8 lanes each)
    scatter1_kernel<<<N_EDGES / 4 * 8 / 256, 256>>>(src, dst);

    // 4. z = relu(agg1 + b1) @ W2 -> half2  (also zeroes agg2h)
    hidden_kernel<<<(N_NODES + 31) / 32, 128>>>(b1, W2);

    // 5. agg2h[dst] += zh[src]  (4 edges/thread, 4 lanes each)
    scatter2_kernel<<<N_EDGES / 4 * 4 / 256, 256>>>(src, dst);

    // 6. out = log_softmax(agg2 + b2)
    lsm_kernel<<<(N_NODES + 15) / 16, 256>>>(b2, out);
}

// round 15
// speedup vs baseline: 1.0296x; 1.0296x over previous
#include <cuda_runtime.h>
#include <cuda_fp16.h>

#define N_NODES 50000
#define N_EDGES 800000
#define IN_F 96
#define HID 64
#define N_CLS 32

// Scratch (__device__ globals, allocation-free rule)
__device__ __align__(16) unsigned g_yh[N_NODES * (HID / 2)];     // y half2     (6.4 MB)
__device__ __align__(16) unsigned g_agg1h[N_NODES * (HID / 2)];  // agg1 half2  (6.4 MB)
__device__ __align__(16) unsigned g_zh[N_NODES * (N_CLS / 2)];   // z half2     (3.2 MB)
__device__ __align__(16) unsigned g_agg2h[N_NODES * (N_CLS / 2)];// agg2 half2  (3.2 MB)

__device__ __forceinline__ void red_add_v4h2(unsigned* p, uint4 v) {
    asm volatile("red.global.add.noftz.v4.f16x2 [%0], {%1,%2,%3,%4};"
                 :: "l"(p), "r"(v.x), "r"(v.y), "r"(v.z), "r"(v.w) : "memory");
}

// Zero agg1h only (400k uint4); agg2h is zeroed inside hidden_kernel.
__global__ void zero_kernel() {
    const int n1 = N_NODES * (HID / 2) / 4;    // 400000
    int i = blockIdx.x * blockDim.x + threadIdx.x;
    if (i < n1) ((uint4*)g_agg1h)[i] = make_uint4(0u, 0u, 0u, 0u);
}

// y = x @ W1 [50000 x 64], output packed half2. 50 nodes/block, 160 threads,
// thread computes 5 nodes x 4 cols (= 2 half2).
__global__ void __launch_bounds__(160) gemm_x_kernel(
        const float* __restrict__ x,
        const float* __restrict__ W1) {
    __shared__ float xs[50 * 100];
    __shared__ float ws[IN_F * HID];
    int tid = threadIdx.x;

    for (int i = tid; i < IN_F * HID / 4; i += 160)
        ((float4*)ws)[i] = __ldg((const float4*)W1 + i);

    const float4* xg = (const float4*)x + blockIdx.x * 50 * (IN_F / 4);
    for (int i = tid; i < 50 * (IN_F / 4); i += 160) {
        int r = i / (IN_F / 4);
        int c = i - r * (IN_F / 4);
        *(float4*)&xs[r * 100 + c * 4] = __ldg(xg + i);
    }
    __syncthreads();

    int tx = tid & 15;
    int ty = tid >> 4;
    float acc[5][4];
#pragma unroll
    for (int i = 0; i < 5; ++i)
#pragma unroll
        for (int j = 0; j < 4; ++j) acc[i][j] = 0.f;

    const float* xbase = &xs[ty * 5 * 100];
#pragma unroll 2
    for (int k = 0; k < IN_F; k += 4) {
        float4 wv0 = *(float4*)&ws[(k + 0) * HID + tx * 4];
        float4 wv1 = *(float4*)&ws[(k + 1) * HID + tx * 4];
        float4 wv2 = *(float4*)&ws[(k + 2) * HID + tx * 4];
        float4 wv3 = *(float4*)&ws[(k + 3) * HID + tx * 4];
#pragma unroll
        for (int i = 0; i < 5; ++i) {
            float4 xv = *(float4*)&xbase[i * 100 + k];
            acc[i][0] = fmaf(xv.x, wv0.x, acc[i][0]);
            acc[i][1] = fmaf(xv.x, wv0.y, acc[i][1]);
            acc[i][2] = fmaf(xv.x, wv0.z, acc[i][2]);
            acc[i][3] = fmaf(xv.x, wv0.w, acc[i][3]);
            acc[i][0] = fmaf(xv.y, wv1.x, acc[i][0]);
            acc[i][1] = fmaf(xv.y, wv1.y, acc[i][1]);
            acc[i][2] = fmaf(xv.y, wv1.z, acc[i][2]);
            acc[i][3] = fmaf(xv.y, wv1.w, acc[i][3]);
            acc[i][0] = fmaf(xv.z, wv2.x, acc[i][0]);
            acc[i][1] = fmaf(xv.z, wv2.y, acc[i][1]);
            acc[i][2] = fmaf(xv.z, wv2.z, acc[i][2]);
            acc[i][3] = fmaf(xv.z, wv2.w, acc[i][3]);
            acc[i][0] = fmaf(xv.w, wv3.x, acc[i][0]);
            acc[i][1] = fmaf(xv.w, wv3.y, acc[i][1]);
            acc[i][2] = fmaf(xv.w, wv3.z, acc[i][2]);
            acc[i][3] = fmaf(xv.w, wv3.w, acc[i][3]);
        }
    }
    int n0 = blockIdx.x * 50 + ty * 5;
#pragma unroll
    for (int i = 0; i < 5; ++i) {
        __half2 h0 = __floats2half2_rn(acc[i][0], acc[i][1]);
        __half2 h1 = __floats2half2_rn(acc[i][2], acc[i][3]);
        uint2 u;
        u.x = *(unsigned*)&h0;
        u.y = *(unsigned*)&h1;
        *(uint2*)&g_yh[(n0 + i) * (HID / 2) + tx * 2] = u;
    }
}

// Layer-1 scatter, 4 edges per thread: agg1h[dst] += yh[src].
// 64 halves = 8 x uint4 lanes per edge. All loads front-batched.
__global__ void scatter1_kernel(const int* __restrict__ src,
                                const int* __restrict__ dst) {
    const int E4 = N_EDGES / 4;   // 200000
    int i = blockIdx.x * blockDim.x + threadIdx.x;
    int e = i >> 3;
    int c = i & 7;
    int s0 = __ldg(src + e);
    int d0 = __ldg(dst + e);
    int s1 = __ldg(src + e + E4);
    int d1 = __ldg(dst + e + E4);
    int s2 = __ldg(src + e + 2 * E4);
    int d2 = __ldg(dst + e + 2 * E4);
    int s3 = __ldg(src + e + 3 * E4);
    int d3 = __ldg(dst + e + 3 * E4);
    uint4 v0 = __ldg((const uint4*)g_yh + s0 * 8 + c);
    uint4 v1 = __ldg((const uint4*)g_yh + s1 * 8 + c);
    uint4 v2 = __ldg((const uint4*)g_yh + s2 * 8 + c);
    uint4 v3 = __ldg((const uint4*)g_yh + s3 * 8 + c);
    red_add_v4h2(g_agg1h + d0 * (HID / 2) + c * 4, v0);
    red_add_v4h2(g_agg1h + d1 * (HID / 2) + c * 4, v1);
    red_add_v4h2(g_agg1h + d2 * (HID / 2) + c * 4, v2);
    red_add_v4h2(g_agg1h + d3 * (HID / 2) + c * 4, v3);
}

// Layer-2 scatter, 4 edges per thread: agg2h[dst] += zh[src].
// 32 halves = 4 x uint4 lanes per edge.
__global__ void scatter2_kernel(const int* __restrict__ src,
                                const int* __restrict__ dst) {
    const int E4 = N_EDGES / 4;
    int i = blockIdx.x * blockDim.x + threadIdx.x;
    int e = i >> 2;
    int c = i & 3;
    int s0 = __ldg(src + e);
    int d0 = __ldg(dst + e);
    int s1 = __ldg(src + e + E4);
    int d1 = __ldg(dst + e + E4);
    int s2 = __ldg(src + e + 2 * E4);
    int d2 = __ldg(dst + e + 2 * E4);
    int s3 = __ldg(src + e + 3 * E4);
    int d3 = __ldg(dst + e + 3 * E4);
    uint4 v0 = __ldg((const uint4*)g_zh + s0 * 4 + c);
    uint4 v1 = __ldg((const uint4*)g_zh + s1 * 4 + c);
    uint4 v2 = __ldg((const uint4*)g_zh + s2 * 4 + c);
    uint4 v3 = __ldg((const uint4*)g_zh + s3 * 4 + c);
    red_add_v4h2(g_agg2h + d0 * (N_CLS / 2) + c * 4, v0);
    red_add_v4h2(g_agg2h + d1 * (N_CLS / 2) + c * 4, v1);
    red_add_v4h2(g_agg2h + d2 * (N_CLS / 2) + c * 4, v2);
    red_add_v4h2(g_agg2h + d3 * (N_CLS / 2) + c * 4, v3);
}

// z = relu(agg1 + b1) @ W2  [50000 x 32] -> half2. 64 nodes/block, 128 threads,
// thread computes a 4-node x 4-col register tile. Also zeroes agg2h slice.
__global__ void __launch_bounds__(128) hidden_kernel(
        const float* __restrict__ b1,
        const float* __restrict__ W2) {
    __shared__ float as[64 * 68];      // 17408 B
    __shared__ float ws[HID * N_CLS];  // 8192 B
    int tid = threadIdx.x;
    int n0 = blockIdx.x * 64;

    // fold: zero agg2h for this block's 64 nodes (4 uint4 per node).
    {
        int base = n0 * 4;               // uint4 index
        const int tot = N_NODES * 4;     // 200000
#pragma unroll
        for (int i = tid; i < 256; i += 128) {
            int j = base + i;
            if (j < tot) ((uint4*)g_agg2h)[j] = make_uint4(0u, 0u, 0u, 0u);
        }
    }

    for (int i = tid; i < HID * N_CLS / 4; i += 128)
        ((float4*)ws)[i] = __ldg((const float4*)W2 + i);

    // stage: 64 rows x 8 uint4 chunks; convert fp16->fp32, +b1, relu.
    for (int i = tid; i < 64 * 8; i += 128) {
        int r = i >> 3;
        int c = i & 7;
        int n = n0 + r;
        float4 f0 = make_float4(0.f, 0.f, 0.f, 0.f);
        float4 f1 = f0;
        if (n < N_NODES) {
            uint4 u = __ldg((const uint4*)g_agg1h + n * 8 + c);
            float2 a0 = __half22float2(*(__half2*)&u.x);
            float2 a1 = __half22float2(*(__half2*)&u.y);
            float2 a2 = __half22float2(*(__half2*)&u.z);
            float2 a3 = __half22float2(*(__half2*)&u.w);
            float4 bb0 = __ldg((const float4*)b1 + c * 2);
            float4 bb1 = __ldg((const float4*)b1 + c * 2 + 1);
            f0.x = fmaxf(a0.x + bb0.x, 0.f);
            f0.y = fmaxf(a0.y + bb0.y, 0.f);
            f0.z = fmaxf(a1.x + bb0.z, 0.f);
            f0.w = fmaxf(a1.y + bb0.w, 0.f);
            f1.x = fmaxf(a2.x + bb1.x, 0.f);
            f1.y = fmaxf(a2.y + bb1.y, 0.f);
            f1.z = fmaxf(a3.x + bb1.z, 0.f);
            f1.w = fmaxf(a3.y + bb1.w, 0.f);
        }
        *(float4*)&as[r * 68 + c * 8]     = f0;
        *(float4*)&as[r * 68 + c * 8 + 4] = f1;
    }
    __syncthreads();

    int tx = tid & 7;    // col group (8 x 4 cols = 32)
    int ty = tid >> 3;   // node group (0..15), 4 nodes each
    float acc[4][4];
#pragma unroll
    for (int i = 0; i < 4; ++i)
#pragma unroll
        for (int j = 0; j < 4; ++j) acc[i][j] = 0.f;

    const float* abase = &as[ty * 4 * 68];
#pragma unroll 2
    for (int k = 0; k < HID; k += 4) {
        float4 wv0 = *(float4*)&ws[(k + 0) * N_CLS + tx * 4];
        float4 wv1 = *(float4*)&ws[(k + 1) * N_CLS + tx * 4];
        float4 wv2 = *(float4*)&ws[(k + 2) * N_CLS + tx * 4];
        float4 wv3 = *(float4*)&ws[(k + 3) * N_CLS + tx * 4];
#pragma unroll
        for (int i = 0; i < 4; ++i) {
            float4 xv = *(float4*)&abase[i * 68 + k];
            acc[i][0] = fmaf(xv.x, wv0.x, acc[i][0]);
            acc[i][1] = fmaf(xv.x, wv0.y, acc[i][1]);
            acc[i][2] = fmaf(xv.x, wv0.z, acc[i][2]);
            acc[i][3] = fmaf(xv.x, wv0.w, acc[i][3]);
            acc[i][0] = fmaf(xv.y, wv1.x, acc[i][0]);
            acc[i][1] = fmaf(xv.y, wv1.y, acc[i][1]);
            acc[i][2] = fmaf(xv.y, wv1.z, acc[i][2]);
            acc[i][3] = fmaf(xv.y, wv1.w, acc[i][3]);
            acc[i][0] = fmaf(xv.z, wv2.x, acc[i][0]);
            acc[i][1] = fmaf(xv.z, wv2.y, acc[i][1]);
            acc[i][2] = fmaf(xv.z, wv2.z, acc[i][2]);
            acc[i][3] = fmaf(xv.z, wv2.w, acc[i][3]);
            acc[i][0] = fmaf(xv.w, wv3.x, acc[i][0]);
            acc[i][1] = fmaf(xv.w, wv3.y, acc[i][1]);
            acc[i][2] = fmaf(xv.w, wv3.z, acc[i][2]);
            acc[i][3] = fmaf(xv.w, wv3.w, acc[i][3]);
        }
    }
#pragma unroll
    for (int i = 0; i < 4; ++i) {
        int n = n0 + ty * 4 + i;
        if (n < N_NODES) {
            __half2 h0 = __floats2half2_rn(acc[i][0], acc[i][1]);
            __half2 h1 = __floats2half2_rn(acc[i][2], acc[i][3]);
            uint2 u;
            u.x = *(unsigned*)&h0;
            u.y = *(unsigned*)&h1;
            *(uint2*)&g_zh[n * (N_CLS / 2) + tx * 2] = u;
        }
    }
}

// out = log_softmax(agg2 + b2). Lane handles 2 classes (half2); 16 lanes/node,
// 2 nodes/warp, 16 nodes per 256-thread block.
__global__ void __launch_bounds__(256) lsm_kernel(
        const float* __restrict__ b2,
        float* __restrict__ out) {
    int tid = threadIdx.x;
    int half_lane = tid & 15;             // class pair index
    int n = blockIdx.x * 16 + (tid >> 4); // node
    unsigned u = g_agg2h[n * (N_CLS / 2) + half_lane];
    float2 a = __half22float2(*(__half2*)&u);
    float2 bb = __ldg((const float2*)b2 + half_lane);
    float v0 = a.x + bb.x;
    float v1 = a.y + bb.y;

    float m = fmaxf(v0, v1);
#pragma unroll
    for (int o = 1; o <= 8; o <<= 1) m = fmaxf(m, __shfl_xor_sync(0xffffffffu, m, o));
    float p = __expf(v0 - m) + __expf(v1 - m);
#pragma unroll
    for (int o = 1; o <= 8; o <<= 1) p += __shfl_xor_sync(0xffffffffu, p, o);
    float lp = m + __logf(p);

    float2 r;
    r.x = v0 - lp;
    r.y = v1 - lp;
    ((float2*)out)[n * (N_CLS / 2) + half_lane] = r;
}

extern "C" void kernel_launch(void* const* d_in, const int* in_sizes, int n_in,
                              void* d_out, int out_size) {
    const float* x  = (const float*)d_in[0];
    const int*   ei = (const int*)d_in[1];   // int32 [2, E]
    const float* W1 = (const float*)d_in[2];
    const float* b1 = (const float*)d_in[3];
    const float* W2 = (const float*)d_in[4];
    const float* b2 = (const float*)d_in[5];
    float* out      = (float*)d_out;

    const int* src = ei;
    const int* dst = ei + N_EDGES;

    // 1. zero agg1h (400k uint4)
    zero_kernel<<<(400000 + 255) / 256, 256>>>();

    // 2. y = x @ W1 -> half2
    gemm_x_kernel<<<N_NODES / 50, 160>>>(x, W1);

    // 3. agg1h[dst] += yh[src]  (4 edges/thread, 8 lanes each)
    scatter1_kernel<<<N_EDGES / 4 * 8 / 256, 256>>>(src, dst);

    // 4. z = relu(agg1 + b1) @ W2 -> half2  (also zeroes agg2h; 64 nodes/block)
    hidden_kernel<<<(N_NODES + 63) / 64, 128>>>(b1, W2);

    // 5. agg2h[dst] += zh[src]  (4 edges/thread, 4 lanes each)
    scatter2_kernel<<<N_EDGES / 4 * 4 / 256, 256>>>(src, dst);

    // 6. out = log_softmax(agg2 + b2)
    lsm_kernel<<<(N_NODES + 15) / 16, 256>>>(b2, out);
}